// round 3
// baseline (speedup 1.0000x reference)
#include <cuda_runtime.h>

#define NN 100000
#define NE 3200000
#define NG 64

// ---------------- scratch (device globals; no allocations allowed) ----------
__device__ float d_deg[NN];          // degree -> dinv (in place)
__device__ float d_norm[NE];
__device__ float d_h1pre[NN * 64];   // x @ W1
__device__ float d_h1out[NN * 64];   // conv1 aggregation (pre bias/relu)
__device__ float d_h2pre[NN * 32];   // relu(h1out+b1) @ W2
__device__ float d_h2out[NN * 32];   // conv2 aggregation (pre bias/relu)
__device__ float d_pooled[NG * 32];

// ---------------- f32x2 helpers (Blackwell packed fp32) ---------------------
__device__ __forceinline__ unsigned long long pk2(float x) {
    unsigned long long r;
    asm("mov.b64 %0, {%1, %1};" : "=l"(r) : "f"(x));
    return r;
}
__device__ __forceinline__ void fma2(unsigned long long& d,
                                     unsigned long long a, unsigned long long b) {
    asm("fma.rn.f32x2 %0, %1, %2, %0;" : "+l"(d) : "l"(a), "l"(b));
}
__device__ __forceinline__ float2 up2(unsigned long long v) {
    float2 f;
    asm("mov.b64 {%0, %1}, %2;" : "=f"(f.x), "=f"(f.y) : "l"(v));
    return f;
}

// ---------------- graph prep ------------------------------------------------
__global__ void k_init() {
    int i = blockIdx.x * 256 + threadIdx.x;
    if (i < NN) d_deg[i] = 1.0f;            // self-loop weight
    if (i < NG * 32) d_pooled[i] = 0.0f;    // relu outputs are >= 0
}

__global__ void k_prep(const int* __restrict__ ei, const float* __restrict__ ew) {
    int e = blockIdx.x * 256 + threadIdx.x;
    if (e >= NE) return;
    atomicAdd(&d_deg[ei[NE + e]], ew[e]);   // dst-degree
}

__global__ void k_rsqrt() {
    int i = blockIdx.x * 256 + threadIdx.x;
    if (i < NN) d_deg[i] = rsqrtf(d_deg[i]);   // deg >= 1 always
}

__global__ void k_norm(const int* __restrict__ ei, const float* __restrict__ ew) {
    int e = blockIdx.x * 256 + threadIdx.x;
    if (e >= NE) return;
    d_norm[e] = d_deg[ei[e]] * ew[e] * d_deg[ei[NE + e]];
}

// ---------------- GEMM: C[n, COLS] = f(A[n, K]) @ W[K, COLS] ----------------
// MODE 1: A = x (arg), C = d_h1pre, no transform.
// MODE 2: A = d_h1out, transform a -> relu(a + b1[k]), C = d_h2pre.
// 256 threads; thread computes 8 rows x 4 cols with f32x2 FMA.
// W staged through smem in K-chunks of 64 rows (16KB max).
template <int K, int COLS, int MODE>
__global__ void __launch_bounds__(256) k_gemm(const float* __restrict__ Aarg,
                                              const float* __restrict__ W,
                                              const float* __restrict__ bias) {
    constexpr int CG = COLS / 4;       // col groups of 4
    constexpr int ROWS = (256 / CG) * 8;
    constexpr int KC = 64;             // K chunk
    __shared__ __align__(16) float Ws[KC * COLS];
    __shared__ __align__(16) float Bs[KC];
    const float* A = (MODE == 1) ? Aarg : d_h1out;
    float* C = (MODE == 1) ? d_h1pre : d_h2pre;

    int t = threadIdx.x;
    int ct = t % CG;
    int rt = t / CG;
    int row0 = blockIdx.x * ROWS + rt * 8;

    const float* ap[8];
#pragma unroll
    for (int i = 0; i < 8; i++) {
        int r = row0 + i;
        if (r > NN - 1) r = NN - 1;       // clamp loads; stores guarded below
        ap[i] = A + (long long)r * K;
    }

    unsigned long long acc[8][2];
#pragma unroll
    for (int i = 0; i < 8; i++) { acc[i][0] = 0ULL; acc[i][1] = 0ULL; }

    for (int k0 = 0; k0 < K; k0 += KC) {
        __syncthreads();
        for (int i = t; i < KC * COLS / 4; i += 256)
            ((float4*)Ws)[i] = ((const float4*)(W + k0 * COLS))[i];
        if (MODE == 2) {
            if (t < KC) Bs[t] = bias[k0 + t];
        }
        __syncthreads();

#pragma unroll 2
        for (int kq = 0; kq < KC / 4; kq++) {
            float4 a[8];
#pragma unroll
            for (int i = 0; i < 8; i++) a[i] = *(const float4*)(ap[i] + k0 + kq * 4);
            if (MODE == 2) {
                float4 b4 = *(const float4*)(Bs + kq * 4);
#pragma unroll
                for (int i = 0; i < 8; i++) {
                    a[i].x = fmaxf(a[i].x + b4.x, 0.0f);
                    a[i].y = fmaxf(a[i].y + b4.y, 0.0f);
                    a[i].z = fmaxf(a[i].z + b4.z, 0.0f);
                    a[i].w = fmaxf(a[i].w + b4.w, 0.0f);
                }
            }
#pragma unroll
            for (int j = 0; j < 4; j++) {
                ulonglong2 w2 = *(const ulonglong2*)(Ws + (kq * 4 + j) * COLS + ct * 4);
#pragma unroll
                for (int i = 0; i < 8; i++) {
                    float av = (j == 0) ? a[i].x : (j == 1) ? a[i].y
                             : (j == 2) ? a[i].z : a[i].w;
                    unsigned long long aa = pk2(av);
                    fma2(acc[i][0], aa, w2.x);
                    fma2(acc[i][1], aa, w2.y);
                }
            }
        }
    }

#pragma unroll
    for (int i = 0; i < 8; i++) {
        int r = row0 + i;
        if (r < NN) {
            float2 p0 = up2(acc[i][0]);
            float2 p1 = up2(acc[i][1]);
            *(float4*)(C + (long long)r * COLS + ct * 4) =
                make_float4(p0.x, p0.y, p1.x, p1.y);
        }
    }
}

// ---------------- self-loop init: out = dinv^2 * pre -------------------------
__global__ void k_selfloop1() {
    int idx = blockIdx.x * 256 + threadIdx.x;   // over NN*16 float4s
    if (idx >= NN * 16) return;
    float f = d_deg[idx >> 4];
    f = f * f;
    float4 v = ((const float4*)d_h1pre)[idx];
    ((float4*)d_h1out)[idx] = make_float4(v.x * f, v.y * f, v.z * f, v.w * f);
}

__global__ void k_selfloop2() {
    int idx = blockIdx.x * 256 + threadIdx.x;   // over NN*8 float4s
    if (idx >= NN * 8) return;
    float f = d_deg[idx >> 3];
    f = f * f;
    float4 v = ((const float4*)d_h2pre)[idx];
    ((float4*)d_h2out)[idx] = make_float4(v.x * f, v.y * f, v.z * f, v.w * f);
}

// ---------------- edge aggregation (scatter via scalar REDG) -----------------
__global__ void k_agg1(const int* __restrict__ ei) {
    int idx = blockIdx.x * 256 + threadIdx.x;   // NE*16 threads
    int e = idx >> 4;
    int g = idx & 15;
    int s = ei[e];
    int d = ei[NE + e];
    float w = d_norm[e];
    float4 v = ((const float4*)d_h1pre)[s * 16 + g];
    float* p = d_h1out + d * 64 + g * 4;
    atomicAdd(p + 0, v.x * w);
    atomicAdd(p + 1, v.y * w);
    atomicAdd(p + 2, v.z * w);
    atomicAdd(p + 3, v.w * w);
}

__global__ void k_agg2(const int* __restrict__ ei) {
    int idx = blockIdx.x * 256 + threadIdx.x;   // NE*8 threads
    int e = idx >> 3;
    int g = idx & 7;
    int s = ei[e];
    int d = ei[NE + e];
    float w = d_norm[e];
    float4 v = ((const float4*)d_h2pre)[s * 8 + g];
    float* p = d_h2out + d * 32 + g * 4;
    atomicAdd(p + 0, v.x * w);
    atomicAdd(p + 1, v.y * w);
    atomicAdd(p + 2, v.z * w);
    atomicAdd(p + 3, v.w * w);
}

// ---------------- pooling: segment_max(relu(h2out + b2)) --------------------
__global__ void k_pool(const int* __restrict__ batch, const float* __restrict__ b2) {
    int idx = blockIdx.x * 256 + threadIdx.x;   // NN*32
    if (idx >= NN * 32) return;
    int i = idx >> 5;
    int c = idx & 31;
    float v = fmaxf(d_h2out[idx] + b2[c], 0.0f);
    int g = batch[i];
    atomicMax((int*)&d_pooled[g * 32 + c], __float_as_int(v));  // v >= 0
}

// ---------------- final linear: out[64,4] = pooled @ Wlin + blin ------------
__global__ void k_final(const float* __restrict__ Wlin, const float* __restrict__ blin,
                        float* __restrict__ out) {
    int t = threadIdx.x;            // 256 = 64*4
    int g = t >> 2;
    int c = t & 3;
    float s = blin[c];
#pragma unroll
    for (int k = 0; k < 32; k++) s += d_pooled[g * 32 + k] * Wlin[k * 4 + c];
    out[g * 4 + c] = s;
}

// ---------------- launch -----------------------------------------------------
extern "C" void kernel_launch(void* const* d_in, const int* in_sizes, int n_in,
                              void* d_out, int out_size) {
    const float* x     = (const float*)d_in[0];
    const int*   ei    = (const int*)d_in[1];     // int32 (JAX x64 disabled)
    const float* ew    = (const float*)d_in[2];
    const int*   batch = (const int*)d_in[3];     // int32
    const float* W1    = (const float*)d_in[4];
    const float* b1    = (const float*)d_in[5];
    const float* W2    = (const float*)d_in[6];
    const float* b2    = (const float*)d_in[7];
    const float* Wlin  = (const float*)d_in[8];
    const float* blin  = (const float*)d_in[9];
    float* out = (float*)d_out;

    k_init<<<(NN + 255) / 256, 256>>>();
    k_prep<<<(NE + 255) / 256, 256>>>(ei, ew);
    k_rsqrt<<<(NN + 255) / 256, 256>>>();
    k_norm<<<(NE + 255) / 256, 256>>>(ei, ew);

    k_gemm<256, 64, 1><<<(NN + 127) / 128, 256>>>(x, W1, nullptr);
    k_selfloop1<<<(NN * 16 + 255) / 256, 256>>>();
    k_agg1<<<(NE * 16) / 256, 256>>>(ei);

    k_gemm<64, 32, 2><<<(NN + 255) / 256, 256>>>(nullptr, W2, b1);
    k_selfloop2<<<(NN * 8 + 255) / 256, 256>>>();
    k_agg2<<<(NE * 8) / 256, 256>>>(ei);

    k_pool<<<(NN * 32 + 255) / 256, 256>>>(batch, b2);
    k_final<<<1, 256>>>(Wlin, blin, out);
}

// round 4
// speedup vs baseline: 1.6276x; 1.6276x over previous
#include <cuda_runtime.h>

#define NN 100000
#define NE 3200000
#define NG 64
#define SCAN_T 1024
#define CHUNK 98              // ceil(NN / SCAN_T)

// ---------------- scratch (device globals; no allocations allowed) ----------
__device__ float d_deg[NN];          // weighted degree -> dinv (in place)
__device__ int   d_cnt[NN];          // edge count per dst
__device__ int   d_ptr[NN + 1];      // CSR row offsets
__device__ int   d_fill[NN];         // scatter cursors
__device__ int2  d_csr[NE];          // {src, __float_as_int(norm)}
__device__ float d_h1pre[NN * 64];   // x @ W1
__device__ float d_h1out[NN * 64];   // conv1 aggregated (pre bias/relu)
__device__ float d_h2pre[NN * 32];   // relu(h1out+b1) @ W2
__device__ float d_h2out[NN * 32];   // conv2 aggregated (pre bias/relu)
__device__ float d_pooled[NG * 32];

// ---------------- f32x2 helpers (Blackwell packed fp32) ---------------------
__device__ __forceinline__ unsigned long long pk2(float x) {
    unsigned long long r;
    asm("mov.b64 %0, {%1, %1};" : "=l"(r) : "f"(x));
    return r;
}
__device__ __forceinline__ void fma2(unsigned long long& d,
                                     unsigned long long a, unsigned long long b) {
    asm("fma.rn.f32x2 %0, %1, %2, %0;" : "+l"(d) : "l"(a), "l"(b));
}
__device__ __forceinline__ float2 up2(unsigned long long v) {
    float2 f;
    asm("mov.b64 {%0, %1}, %2;" : "=f"(f.x), "=f"(f.y) : "l"(v));
    return f;
}

// ---------------- graph prep ------------------------------------------------
__global__ void k_init() {
    int i = blockIdx.x * 256 + threadIdx.x;
    if (i < NN) { d_deg[i] = 1.0f; d_cnt[i] = 0; }   // self-loop weight 1
    if (i < NG * 32) d_pooled[i] = 0.0f;             // relu outputs >= 0
}

__global__ void k_hist(const int* __restrict__ ei, const float* __restrict__ ew) {
    int e = blockIdx.x * 256 + threadIdx.x;
    if (e >= NE) return;
    int d = ei[NE + e];
    atomicAdd(&d_deg[d], ew[e]);
    atomicAdd(&d_cnt[d], 1);
}

__global__ void k_rsqrt() {
    int i = blockIdx.x * 256 + threadIdx.x;
    if (i < NN) d_deg[i] = rsqrtf(d_deg[i]);   // deg >= 1 always
}

// single-block exclusive scan of d_cnt -> d_ptr (+ copy to d_fill)
__global__ void __launch_bounds__(SCAN_T) k_scan() {
    __shared__ int sums[SCAN_T];
    int t = threadIdx.x;
    int start = t * CHUNK;
    int end = start + CHUNK < NN ? start + CHUNK : NN;
    int s = 0;
    for (int i = start; i < end; i++) s += d_cnt[i];
    sums[t] = s;
    __syncthreads();
    for (int off = 1; off < SCAN_T; off <<= 1) {
        int v = (t >= off) ? sums[t - off] : 0;
        __syncthreads();
        sums[t] += v;
        __syncthreads();
    }
    int run = t ? sums[t - 1] : 0;
    for (int i = start; i < end; i++) {
        d_ptr[i] = run;
        d_fill[i] = run;
        run += d_cnt[i];
    }
    if (t == SCAN_T - 1) d_ptr[NN] = run;   // == NE
}

__global__ void k_scatter(const int* __restrict__ ei, const float* __restrict__ ew) {
    int e = blockIdx.x * 256 + threadIdx.x;
    if (e >= NE) return;
    int s = ei[e];
    int d = ei[NE + e];
    float w = d_deg[s] * ew[e] * d_deg[d];
    int pos = atomicAdd(&d_fill[d], 1);
    d_csr[pos] = make_int2(s, __float_as_int(w));
}

// ---------------- GEMM: C[n, COLS] = f(A[n, K]) @ W[K, COLS] ----------------
template <int K, int COLS, int MODE>
__global__ void __launch_bounds__(256) k_gemm(const float* __restrict__ Aarg,
                                              const float* __restrict__ W,
                                              const float* __restrict__ bias) {
    constexpr int CG = COLS / 4;
    constexpr int ROWS = (256 / CG) * 8;
    constexpr int KC = 64;
    __shared__ __align__(16) float Ws[KC * COLS];
    __shared__ __align__(16) float Bs[KC];
    const float* A = (MODE == 1) ? Aarg : d_h1out;
    float* C = (MODE == 1) ? d_h1pre : d_h2pre;

    int t = threadIdx.x;
    int ct = t % CG;
    int rt = t / CG;
    int row0 = blockIdx.x * ROWS + rt * 8;

    const float* ap[8];
#pragma unroll
    for (int i = 0; i < 8; i++) {
        int r = row0 + i;
        if (r > NN - 1) r = NN - 1;
        ap[i] = A + (long long)r * K;
    }

    unsigned long long acc[8][2];
#pragma unroll
    for (int i = 0; i < 8; i++) { acc[i][0] = 0ULL; acc[i][1] = 0ULL; }

    for (int k0 = 0; k0 < K; k0 += KC) {
        __syncthreads();
        for (int i = t; i < KC * COLS / 4; i += 256)
            ((float4*)Ws)[i] = ((const float4*)(W + k0 * COLS))[i];
        if (MODE == 2) {
            if (t < KC) Bs[t] = bias[k0 + t];
        }
        __syncthreads();

#pragma unroll 2
        for (int kq = 0; kq < KC / 4; kq++) {
            float4 a[8];
#pragma unroll
            for (int i = 0; i < 8; i++) a[i] = *(const float4*)(ap[i] + k0 + kq * 4);
            if (MODE == 2) {
                float4 b4 = *(const float4*)(Bs + kq * 4);
#pragma unroll
                for (int i = 0; i < 8; i++) {
                    a[i].x = fmaxf(a[i].x + b4.x, 0.0f);
                    a[i].y = fmaxf(a[i].y + b4.y, 0.0f);
                    a[i].z = fmaxf(a[i].z + b4.z, 0.0f);
                    a[i].w = fmaxf(a[i].w + b4.w, 0.0f);
                }
            }
#pragma unroll
            for (int j = 0; j < 4; j++) {
                ulonglong2 w2 = *(const ulonglong2*)(Ws + (kq * 4 + j) * COLS + ct * 4);
#pragma unroll
                for (int i = 0; i < 8; i++) {
                    float av = (j == 0) ? a[i].x : (j == 1) ? a[i].y
                             : (j == 2) ? a[i].z : a[i].w;
                    unsigned long long aa = pk2(av);
                    fma2(acc[i][0], aa, w2.x);
                    fma2(acc[i][1], aa, w2.y);
                }
            }
        }
    }

#pragma unroll
    for (int i = 0; i < 8; i++) {
        int r = row0 + i;
        if (r < NN) {
            float2 p0 = up2(acc[i][0]);
            float2 p1 = up2(acc[i][1]);
            *(float4*)(C + (long long)r * COLS + ct * 4) =
                make_float4(p0.x, p0.y, p1.x, p1.y);
        }
    }
}

// ---------------- CSR gather aggregation: warp per node ---------------------
// Layer 1: 64 features, lane holds float2. Self-loop folded into init.
__global__ void __launch_bounds__(256) k_agg1() {
    int node = blockIdx.x * 8 + (threadIdx.x >> 5);
    if (node >= NN) return;
    int lane = threadIdx.x & 31;

    float dv = d_deg[node];
    float sl = dv * dv;
    float2 acc = ((const float2*)d_h1pre)[node * 32 + lane];
    acc.x *= sl; acc.y *= sl;

    int beg = d_ptr[node], end = d_ptr[node + 1];
    for (int base = beg; base < end; base += 32) {
        int2 ed = (base + lane < end) ? d_csr[base + lane] : make_int2(0, 0);
        int cnt = end - base; if (cnt > 32) cnt = 32;
        for (int j = 0; j < cnt; j++) {
            int   s = __shfl_sync(0xffffffffu, ed.x, j);
            float w = __int_as_float(__shfl_sync(0xffffffffu, ed.y, j));
            float2 v = ((const float2*)d_h1pre)[s * 32 + lane];
            acc.x = fmaf(w, v.x, acc.x);
            acc.y = fmaf(w, v.y, acc.y);
        }
    }
    ((float2*)d_h1out)[node * 32 + lane] = acc;
}

// Layer 2: 32 features, lane holds 1 float.
__global__ void __launch_bounds__(256) k_agg2() {
    int node = blockIdx.x * 8 + (threadIdx.x >> 5);
    if (node >= NN) return;
    int lane = threadIdx.x & 31;

    float dv = d_deg[node];
    float acc = d_h2pre[node * 32 + lane] * dv * dv;

    int beg = d_ptr[node], end = d_ptr[node + 1];
    for (int base = beg; base < end; base += 32) {
        int2 ed = (base + lane < end) ? d_csr[base + lane] : make_int2(0, 0);
        int cnt = end - base; if (cnt > 32) cnt = 32;
        for (int j = 0; j < cnt; j++) {
            int   s = __shfl_sync(0xffffffffu, ed.x, j);
            float w = __int_as_float(__shfl_sync(0xffffffffu, ed.y, j));
            acc = fmaf(w, d_h2pre[s * 32 + lane], acc);
        }
    }
    d_h2out[node * 32 + lane] = acc;
}

// ---------------- pooling: segment_max(relu(h2out + b2)), batch sorted ------
#define PN 16   // nodes per thread-group pass
__global__ void k_pool(const int* __restrict__ batch, const float* __restrict__ b2) {
    int tid = blockIdx.x * 256 + threadIdx.x;     // (NN/PN)*32 threads
    int c = tid & 31;
    int n0 = (tid >> 5) * PN;
    if (n0 >= NN) return;
    int nend = n0 + PN < NN ? n0 + PN : NN;
    float bb = b2[c];
    int g = batch[n0];
    float m = 0.0f;
    for (int n = n0; n < nend; n++) {
        int gn = batch[n];
        if (gn != g) {
            atomicMax((int*)&d_pooled[g * 32 + c], __float_as_int(m));
            g = gn; m = 0.0f;
        }
        float v = fmaxf(d_h2out[n * 32 + c] + bb, 0.0f);
        m = fmaxf(m, v);
    }
    atomicMax((int*)&d_pooled[g * 32 + c], __float_as_int(m));
}

// ---------------- final linear: out[64,4] = pooled @ Wlin + blin ------------
__global__ void k_final(const float* __restrict__ Wlin, const float* __restrict__ blin,
                        float* __restrict__ out) {
    int t = threadIdx.x;            // 256 = 64*4
    int g = t >> 2;
    int c = t & 3;
    float s = blin[c];
#pragma unroll
    for (int k = 0; k < 32; k++) s += d_pooled[g * 32 + k] * Wlin[k * 4 + c];
    out[g * 4 + c] = s;
}

// ---------------- launch -----------------------------------------------------
extern "C" void kernel_launch(void* const* d_in, const int* in_sizes, int n_in,
                              void* d_out, int out_size) {
    const float* x     = (const float*)d_in[0];
    const int*   ei    = (const int*)d_in[1];     // int32
    const float* ew    = (const float*)d_in[2];
    const int*   batch = (const int*)d_in[3];     // int32
    const float* W1    = (const float*)d_in[4];
    const float* b1    = (const float*)d_in[5];
    const float* W2    = (const float*)d_in[6];
    const float* b2    = (const float*)d_in[7];
    const float* Wlin  = (const float*)d_in[8];
    const float* blin  = (const float*)d_in[9];
    float* out = (float*)d_out;

    k_init<<<(NN + 255) / 256, 256>>>();
    k_hist<<<(NE + 255) / 256, 256>>>(ei, ew);
    k_rsqrt<<<(NN + 255) / 256, 256>>>();
    k_scan<<<1, SCAN_T>>>();
    k_scatter<<<(NE + 255) / 256, 256>>>(ei, ew);

    k_gemm<256, 64, 1><<<(NN + 127) / 128, 256>>>(x, W1, nullptr);
    k_agg1<<<(NN + 7) / 8, 256>>>();

    k_gemm<64, 32, 2><<<(NN + 255) / 256, 256>>>(nullptr, W2, b1);
    k_agg2<<<(NN + 7) / 8, 256>>>();

    k_pool<<<((NN / PN + 1) * 32 + 255) / 256, 256>>>(batch, b2);
    k_final<<<1, 256>>>(Wlin, blin, out);
}

// round 5
// speedup vs baseline: 2.3030x; 1.4150x over previous
#include <cuda_runtime.h>

#define NN 100000
#define NE 3200000
#define NG 64
#define NB 100               // scan blocks
#define NPB 1000             // nodes per scan block (NB*NPB == NN)

// ---------------- scratch (device globals; no allocations allowed) ----------
__device__ float d_deg[NN];          // weighted degree -> dinv (in place)
__device__ int   d_cnt[NN];          // edge count per dst
__device__ int   d_ptr[NN + 1];      // CSR row offsets
__device__ int   d_fill[NN];         // scatter cursors
__device__ int   d_bsum[NB];         // per-block count totals
__device__ int   d_boff[NB];         // exclusive block offsets
__device__ int2  d_csr[NE];          // {src, __float_as_int(norm)}
__device__ float d_h1pre[NN * 64];   // x @ W1
__device__ float d_h1out[NN * 64];   // conv1 aggregated (pre bias/relu)
__device__ float d_h2pre[NN * 32];   // relu(h1out+b1) @ W2
__device__ float d_h2out[NN * 32];   // conv2 aggregated (pre bias/relu)
__device__ float d_pooled[NG * 32];

// ---------------- f32x2 helpers (Blackwell packed fp32) ---------------------
__device__ __forceinline__ unsigned long long pk2(float x) {
    unsigned long long r;
    asm("mov.b64 %0, {%1, %1};" : "=l"(r) : "f"(x));
    return r;
}
__device__ __forceinline__ void fma2(unsigned long long& d,
                                     unsigned long long a, unsigned long long b) {
    asm("fma.rn.f32x2 %0, %1, %2, %0;" : "+l"(d) : "l"(a), "l"(b));
}
__device__ __forceinline__ float2 up2(unsigned long long v) {
    float2 f;
    asm("mov.b64 {%0, %1}, %2;" : "=f"(f.x), "=f"(f.y) : "l"(v));
    return f;
}

// ---------------- graph prep ------------------------------------------------
__global__ void k_init() {
    int i = blockIdx.x * 256 + threadIdx.x;
    if (i < NN) { d_deg[i] = 1.0f; d_cnt[i] = 0; }   // self-loop weight 1
    if (i < NG * 32) d_pooled[i] = 0.0f;             // relu outputs >= 0
}

__global__ void k_hist(const int* __restrict__ ei, const float* __restrict__ ew) {
    int e = blockIdx.x * 256 + threadIdx.x;
    if (e >= NE) return;
    int d = ei[NE + e];
    atomicAdd(&d_deg[d], ew[e]);
    atomicAdd(&d_cnt[d], 1);
}

__global__ void k_rsqrt() {
    int i = blockIdx.x * 256 + threadIdx.x;
    if (i < NN) d_deg[i] = rsqrtf(d_deg[i]);   // deg >= 1 always
}

// ---- hierarchical scan of d_cnt -> d_ptr (exclusive), d_fill = d_ptr -------
__global__ void __launch_bounds__(256) k_scanA() {    // per-block totals
    __shared__ int sm[8];
    int b = blockIdx.x, t = threadIdx.x;
    int s = 0;
    for (int i = t; i < NPB; i += 256) s += d_cnt[b * NPB + i];
#pragma unroll
    for (int o = 16; o; o >>= 1) s += __shfl_xor_sync(0xffffffffu, s, o);
    if ((t & 31) == 0) sm[t >> 5] = s;
    __syncthreads();
    if (t == 0) {
        int tot = 0;
#pragma unroll
        for (int i = 0; i < 8; i++) tot += sm[i];
        d_bsum[b] = tot;
    }
}

__global__ void __launch_bounds__(128) k_scanB() {    // scan 100 partials
    __shared__ int sm[128];
    int t = threadIdx.x;
    sm[t] = (t < NB) ? d_bsum[t] : 0;
    __syncthreads();
#pragma unroll
    for (int off = 1; off < 128; off <<= 1) {
        int v = (t >= off) ? sm[t - off] : 0;
        __syncthreads();
        sm[t] += v;
        __syncthreads();
    }
    if (t < NB) d_boff[t] = sm[t] - d_bsum[t];   // exclusive
    if (t == 0) d_ptr[NN] = NE;
}

__global__ void __launch_bounds__(256) k_scanC() {    // in-block scan + write
    __shared__ int sm[256];
    int b = blockIdx.x, t = threadIdx.x;
    int base = b * NPB;
    // 4 consecutive counts per thread (250 threads active)
    int4 c = make_int4(0, 0, 0, 0);
    if (t < NPB / 4) c = ((const int4*)(d_cnt + base))[t];
    int tsum = c.x + c.y + c.z + c.w;
    sm[t] = tsum;
    __syncthreads();
#pragma unroll
    for (int off = 1; off < 256; off <<= 1) {
        int v = (t >= off) ? sm[t - off] : 0;
        __syncthreads();
        sm[t] += v;
        __syncthreads();
    }
    if (t < NPB / 4) {
        int run = d_boff[b] + sm[t] - tsum;
        int i = base + t * 4;
        d_ptr[i] = run;     d_fill[i] = run;     run += c.x;
        d_ptr[i + 1] = run; d_fill[i + 1] = run; run += c.y;
        d_ptr[i + 2] = run; d_fill[i + 2] = run; run += c.z;
        d_ptr[i + 3] = run; d_fill[i + 3] = run;
    }
}

__global__ void k_scatter(const int* __restrict__ ei, const float* __restrict__ ew) {
    int e = blockIdx.x * 256 + threadIdx.x;
    if (e >= NE) return;
    int s = ei[e];
    int d = ei[NE + e];
    float w = d_deg[s] * ew[e] * d_deg[d];
    int pos = atomicAdd(&d_fill[d], 1);
    d_csr[pos] = make_int2(s, __float_as_int(w));
}

// ---------------- GEMM: C[n, COLS] = f(A[n, K]) @ W[K, COLS] ----------------
template <int K, int COLS, int MODE>
__global__ void __launch_bounds__(256) k_gemm(const float* __restrict__ Aarg,
                                              const float* __restrict__ W,
                                              const float* __restrict__ bias) {
    constexpr int CG = COLS / 4;
    constexpr int ROWS = (256 / CG) * 8;
    constexpr int KC = 64;
    __shared__ __align__(16) float Ws[KC * COLS];
    __shared__ __align__(16) float Bs[KC];
    const float* A = (MODE == 1) ? Aarg : d_h1out;
    float* C = (MODE == 1) ? d_h1pre : d_h2pre;

    int t = threadIdx.x;
    int ct = t % CG;
    int rt = t / CG;
    int row0 = blockIdx.x * ROWS + rt * 8;

    const float* ap[8];
#pragma unroll
    for (int i = 0; i < 8; i++) {
        int r = row0 + i;
        if (r > NN - 1) r = NN - 1;
        ap[i] = A + (long long)r * K;
    }

    unsigned long long acc[8][2];
#pragma unroll
    for (int i = 0; i < 8; i++) { acc[i][0] = 0ULL; acc[i][1] = 0ULL; }

    for (int k0 = 0; k0 < K; k0 += KC) {
        __syncthreads();
        for (int i = t; i < KC * COLS / 4; i += 256)
            ((float4*)Ws)[i] = ((const float4*)(W + k0 * COLS))[i];
        if (MODE == 2) {
            if (t < KC) Bs[t] = bias[k0 + t];
        }
        __syncthreads();

#pragma unroll 2
        for (int kq = 0; kq < KC / 4; kq++) {
            float4 a[8];
#pragma unroll
            for (int i = 0; i < 8; i++) a[i] = *(const float4*)(ap[i] + k0 + kq * 4);
            if (MODE == 2) {
                float4 b4 = *(const float4*)(Bs + kq * 4);
#pragma unroll
                for (int i = 0; i < 8; i++) {
                    a[i].x = fmaxf(a[i].x + b4.x, 0.0f);
                    a[i].y = fmaxf(a[i].y + b4.y, 0.0f);
                    a[i].z = fmaxf(a[i].z + b4.z, 0.0f);
                    a[i].w = fmaxf(a[i].w + b4.w, 0.0f);
                }
            }
#pragma unroll
            for (int j = 0; j < 4; j++) {
                ulonglong2 w2 = *(const ulonglong2*)(Ws + (kq * 4 + j) * COLS + ct * 4);
#pragma unroll
                for (int i = 0; i < 8; i++) {
                    float av = (j == 0) ? a[i].x : (j == 1) ? a[i].y
                             : (j == 2) ? a[i].z : a[i].w;
                    unsigned long long aa = pk2(av);
                    fma2(acc[i][0], aa, w2.x);
                    fma2(acc[i][1], aa, w2.y);
                }
            }
        }
    }

#pragma unroll
    for (int i = 0; i < 8; i++) {
        int r = row0 + i;
        if (r < NN) {
            float2 p0 = up2(acc[i][0]);
            float2 p1 = up2(acc[i][1]);
            *(float4*)(C + (long long)r * COLS + ct * 4) =
                make_float4(p0.x, p0.y, p1.x, p1.y);
        }
    }
}

// ---------------- CSR gather aggregation: warp per node ---------------------
__global__ void __launch_bounds__(256) k_agg1() {
    int node = blockIdx.x * 8 + (threadIdx.x >> 5);
    if (node >= NN) return;
    int lane = threadIdx.x & 31;

    float dv = d_deg[node];
    float sl = dv * dv;
    float2 acc = ((const float2*)d_h1pre)[node * 32 + lane];
    acc.x *= sl; acc.y *= sl;

    int beg = d_ptr[node], end = d_ptr[node + 1];
    for (int base = beg; base < end; base += 32) {
        int2 ed = (base + lane < end) ? d_csr[base + lane] : make_int2(0, 0);
        int cnt = end - base; if (cnt > 32) cnt = 32;
        for (int j = 0; j < cnt; j++) {
            int   s = __shfl_sync(0xffffffffu, ed.x, j);
            float w = __int_as_float(__shfl_sync(0xffffffffu, ed.y, j));
            float2 v = ((const float2*)d_h1pre)[s * 32 + lane];
            acc.x = fmaf(w, v.x, acc.x);
            acc.y = fmaf(w, v.y, acc.y);
        }
    }
    ((float2*)d_h1out)[node * 32 + lane] = acc;
}

__global__ void __launch_bounds__(256) k_agg2() {
    int node = blockIdx.x * 8 + (threadIdx.x >> 5);
    if (node >= NN) return;
    int lane = threadIdx.x & 31;

    float dv = d_deg[node];
    float acc = d_h2pre[node * 32 + lane] * dv * dv;

    int beg = d_ptr[node], end = d_ptr[node + 1];
    for (int base = beg; base < end; base += 32) {
        int2 ed = (base + lane < end) ? d_csr[base + lane] : make_int2(0, 0);
        int cnt = end - base; if (cnt > 32) cnt = 32;
        for (int j = 0; j < cnt; j++) {
            int   s = __shfl_sync(0xffffffffu, ed.x, j);
            float w = __int_as_float(__shfl_sync(0xffffffffu, ed.y, j));
            acc = fmaf(w, d_h2pre[s * 32 + lane], acc);
        }
    }
    d_h2out[node * 32 + lane] = acc;
}

// ---------------- pooling: segment_max(relu(h2out + b2)), batch sorted ------
#define PN 16   // nodes per thread-group pass
__global__ void k_pool(const int* __restrict__ batch, const float* __restrict__ b2) {
    int tid = blockIdx.x * 256 + threadIdx.x;     // (NN/PN)*32 threads
    int c = tid & 31;
    int n0 = (tid >> 5) * PN;
    if (n0 >= NN) return;
    int nend = n0 + PN < NN ? n0 + PN : NN;
    float bb = b2[c];
    int g = batch[n0];
    float m = 0.0f;
    for (int n = n0; n < nend; n++) {
        int gn = batch[n];
        if (gn != g) {
            atomicMax((int*)&d_pooled[g * 32 + c], __float_as_int(m));
            g = gn; m = 0.0f;
        }
        float v = fmaxf(d_h2out[n * 32 + c] + bb, 0.0f);
        m = fmaxf(m, v);
    }
    atomicMax((int*)&d_pooled[g * 32 + c], __float_as_int(m));
}

// ---------------- final linear: out[64,4] = pooled @ Wlin + blin ------------
__global__ void k_final(const float* __restrict__ Wlin, const float* __restrict__ blin,
                        float* __restrict__ out) {
    int t = threadIdx.x;            // 256 = 64*4
    int g = t >> 2;
    int c = t & 3;
    float s = blin[c];
#pragma unroll
    for (int k = 0; k < 32; k++) s += d_pooled[g * 32 + k] * Wlin[k * 4 + c];
    out[g * 4 + c] = s;
}

// ---------------- launch -----------------------------------------------------
extern "C" void kernel_launch(void* const* d_in, const int* in_sizes, int n_in,
                              void* d_out, int out_size) {
    const float* x     = (const float*)d_in[0];
    const int*   ei    = (const int*)d_in[1];     // int32
    const float* ew    = (const float*)d_in[2];
    const int*   batch = (const int*)d_in[3];     // int32
    const float* W1    = (const float*)d_in[4];
    const float* b1    = (const float*)d_in[5];
    const float* W2    = (const float*)d_in[6];
    const float* b2    = (const float*)d_in[7];
    const float* Wlin  = (const float*)d_in[8];
    const float* blin  = (const float*)d_in[9];
    float* out = (float*)d_out;

    k_init<<<(NN + 255) / 256, 256>>>();
    k_hist<<<(NE + 255) / 256, 256>>>(ei, ew);
    k_rsqrt<<<(NN + 255) / 256, 256>>>();
    k_scanA<<<NB, 256>>>();
    k_scanB<<<1, 128>>>();
    k_scanC<<<NB, 256>>>();
    k_scatter<<<(NE + 255) / 256, 256>>>(ei, ew);

    k_gemm<256, 64, 1><<<(NN + 127) / 128, 256>>>(x, W1, nullptr);
    k_agg1<<<(NN + 7) / 8, 256>>>();

    k_gemm<64, 32, 2><<<(NN + 255) / 256, 256>>>(nullptr, W2, b1);
    k_agg2<<<(NN + 7) / 8, 256>>>();

    k_pool<<<((NN / PN + 1) * 32 + 255) / 256, 256>>>(batch, b2);
    k_final<<<1, 256>>>(Wlin, blin, out);
}